// round 1
// baseline (speedup 1.0000x reference)
#include <cuda_runtime.h>

#define NN   50000
#define NE   1250000
#define HID  64
#define NL   3
#define NG   64
#define EPSV 1e-5f

// -------- device scratch (no runtime allocation allowed) --------
__device__ float d_h[NN * HID];
__device__ float d_m[NN * HID];
__device__ int   d_es[NE];       // src ids grouped by dst
__device__ float d_ew[NE];       // weights grouped by dst
__device__ int   d_deg[NN];
__device__ int   d_ptr[NN + 1];
__device__ int   d_cur[NN];
__device__ float d_psum[NG * HID];
__device__ int   d_pmax[NG * HID];   // float bits; values are >=0 so int-max works
__device__ int   d_pcnt[NG];

// -------- zero the per-launch scratch --------
__global__ void zero_kernel() {
    int i = blockIdx.x * blockDim.x + threadIdx.x;
    int stride = gridDim.x * blockDim.x;
    for (int k = i; k < NN; k += stride) d_deg[k] = 0;
    for (int k = i; k < NG * HID; k += stride) { d_psum[k] = 0.f; d_pmax[k] = 0; }
    if (i < NG) d_pcnt[i] = 0;
}

// -------- CSR build: count degrees of dst --------
__global__ void count_kernel(const int* __restrict__ dst, int ne) {
    int e = blockIdx.x * blockDim.x + threadIdx.x;
    if (e < ne) atomicAdd(&d_deg[dst[e]], 1);
}

// -------- single-block exclusive scan over degrees --------
__global__ void scan_kernel(int n) {
    __shared__ int sm[1024];
    const int CH = (NN + 1023) / 1024;  // 49
    int t = threadIdx.x;
    int start = t * CH;
    int s = 0;
    for (int i = 0; i < CH; i++) {
        int idx = start + i;
        if (idx < n) s += d_deg[idx];
    }
    sm[t] = s;
    __syncthreads();
    // Hillis-Steele inclusive scan
    for (int off = 1; off < 1024; off <<= 1) {
        int v = (t >= off) ? sm[t - off] : 0;
        __syncthreads();
        sm[t] += v;
        __syncthreads();
    }
    int run = (t == 0) ? 0 : sm[t - 1];
    for (int i = 0; i < CH; i++) {
        int idx = start + i;
        if (idx < n) {
            d_ptr[idx] = run;
            d_cur[idx] = run;
            run += d_deg[idx];
        }
    }
    if (t == 1023) d_ptr[n] = sm[1023];
}

// -------- CSR build: scatter edges grouped by dst --------
__global__ void scatter_kernel(const int* __restrict__ src, const int* __restrict__ dst,
                               const float* __restrict__ w, int ne) {
    int e = blockIdx.x * blockDim.x + threadIdx.x;
    if (e < ne) {
        int d = dst[e];
        int p = atomicAdd(&d_cur[d], 1);
        d_es[p] = src[e];
        d_ew[p] = w[e];
    }
}

// -------- m = h @ W  (W 64x64 in smem, one warp per row, shfl-broadcast h) ----
__global__ void gemm_kernel(const float* __restrict__ hin, const float* __restrict__ W,
                            float* __restrict__ mout, int n) {
    __shared__ float Ws[HID * HID];
    int t = threadIdx.x;
    for (int i = t; i < HID * HID; i += blockDim.x) Ws[i] = W[i];
    __syncthreads();
    int warp = t >> 5, lane = t & 31;
    int nwarp = blockDim.x >> 5;
    for (int row = blockIdx.x * nwarp + warp; row < n; row += gridDim.x * nwarp) {
        float2 h2 = ((const float2*)(hin + row * HID))[lane];
        float2 acc = make_float2(0.f, 0.f);
#pragma unroll
        for (int k2 = 0; k2 < 32; k2++) {
            float hx = __shfl_sync(0xffffffffu, h2.x, k2);
            float hy = __shfl_sync(0xffffffffu, h2.y, k2);
            float2 w0 = ((const float2*)(Ws + (2 * k2) * HID))[lane];
            float2 w1 = ((const float2*)(Ws + (2 * k2 + 1) * HID))[lane];
            acc.x += hx * w0.x;  acc.y += hx * w0.y;
            acc.x += hy * w1.x;  acc.y += hy * w1.y;
        }
        ((float2*)(mout + row * HID))[lane] = acc;
    }
}

// -------- per-node aggregation + bias + LayerNorm + ReLU (one warp per node) --
__global__ void aggregate_kernel(const float* __restrict__ m,
                                 const float* __restrict__ cB,
                                 const float* __restrict__ lg,
                                 const float* __restrict__ lb,
                                 float* __restrict__ hout, int n) {
    int gwarp = (blockIdx.x * blockDim.x + threadIdx.x) >> 5;
    int lane = threadIdx.x & 31;
    if (gwarp >= n) return;
    int beg = d_ptr[gwarp], end = d_ptr[gwarp + 1];
    float ax = 0.f, ay = 0.f;
    for (int e = beg; e < end; e++) {
        int s = d_es[e];
        float w = d_ew[e];
        float2 v = ((const float2*)(m + s * HID))[lane];
        ax += v.x * w;
        ay += v.y * w;
    }
    ax += cB[2 * lane];
    ay += cB[2 * lane + 1];
    // mean over 64
    float sum = ax + ay;
#pragma unroll
    for (int o = 16; o > 0; o >>= 1) sum += __shfl_xor_sync(0xffffffffu, sum, o);
    float mu = sum * (1.f / 64.f);
    float dx = ax - mu, dy = ay - mu;
    float v2 = dx * dx + dy * dy;
#pragma unroll
    for (int o = 16; o > 0; o >>= 1) v2 += __shfl_xor_sync(0xffffffffu, v2, o);
    float inv = rsqrtf(v2 * (1.f / 64.f) + EPSV);
    float rx = fmaxf(dx * inv * lg[2 * lane] + lb[2 * lane], 0.f);
    float ry = fmaxf(dy * inv * lg[2 * lane + 1] + lb[2 * lane + 1], 0.f);
    ((float2*)(hout + gwarp * HID))[lane] = make_float2(rx, ry);
}

// -------- pooling: per-graph sum / max / count --------
__global__ void pool_kernel(const float* __restrict__ h, const int* __restrict__ batch, int n) {
    int idx = blockIdx.x * blockDim.x + threadIdx.x;
    int node = idx >> 6;
    int c = idx & 63;
    if (node >= n) return;
    int b = batch[node];
    float v = h[idx];
    atomicAdd(&d_psum[b * HID + c], v);
    atomicMax(&d_pmax[b * HID + c], __float_as_int(v));
    if (c == 0) atomicAdd(&d_pcnt[b], 1);
}

// -------- final MLP: out[g] = relu([mean||max] @ W1 + b1) @ W2 + b2 --------
__global__ void mlp_kernel(const float* __restrict__ W1, const float* __restrict__ b1,
                           const float* __restrict__ W2, const float* __restrict__ b2,
                           float* __restrict__ out) {
    __shared__ float g[2 * HID];
    __shared__ float hr[HID];
    int gi = blockIdx.x, j = threadIdx.x;
    int cnt = d_pcnt[gi];
    float c = fmaxf((float)cnt, 1.f);
    g[j] = d_psum[gi * HID + j] / c;
    g[HID + j] = (cnt > 0) ? __int_as_float(d_pmax[gi * HID + j]) : 0.f;
    __syncthreads();
    float acc = b1[j];
#pragma unroll
    for (int k = 0; k < 2 * HID; k++) acc += g[k] * W1[k * HID + j];
    acc = fmaxf(acc, 0.f);
    hr[j] = acc * W2[j];
    __syncthreads();
    if (j < 32) {
        float s = hr[j] + hr[j + 32];
#pragma unroll
        for (int o = 16; o > 0; o >>= 1) s += __shfl_xor_sync(0xffffffffu, s, o);
        if (j == 0) out[gi] = s + b2[0];
    }
}

extern "C" void kernel_launch(void* const* d_in, const int* in_sizes, int n_in,
                              void* d_out, int out_size) {
    // input order: x, edge_index, edge_weight, batch, emb, convW, convB, lnG, lnB, W1, b1, W2, b2
    const int*   edge_index = (const int*)d_in[1];
    const float* edge_w     = (const float*)d_in[2];
    const int*   batch      = (const int*)d_in[3];
    const float* emb        = (const float*)d_in[4];
    const float* convW      = (const float*)d_in[5];
    const float* convB      = (const float*)d_in[6];
    const float* lnG        = (const float*)d_in[7];
    const float* lnB        = (const float*)d_in[8];
    const float* W1         = (const float*)d_in[9];
    const float* b1         = (const float*)d_in[10];
    const float* W2         = (const float*)d_in[11];
    const float* b2         = (const float*)d_in[12];
    float* out = (float*)d_out;

    int ne = in_sizes[2];            // N_EDGES
    int n  = in_sizes[3];            // N_NODES
    const int* src = edge_index;
    const int* dst = edge_index + ne;

    // resolve device-global pointers for kernels that take them as args
    float *h_buf, *m_buf;
    cudaGetSymbolAddress((void**)&h_buf, d_h);
    cudaGetSymbolAddress((void**)&m_buf, d_m);

    zero_kernel<<<256, 256>>>();
    count_kernel<<<(ne + 255) / 256, 256>>>(dst, ne);
    scan_kernel<<<1, 1024>>>(n);
    scatter_kernel<<<(ne + 255) / 256, 256>>>(src, dst, edge_w, ne);

    int gemm_blocks = (n + 7) / 8;               // 8 warps (rows) per block
    int agg_blocks  = (n + 7) / 8;               // 8 warps (nodes) per block

    for (int L = 0; L < NL; L++) {
        const float* hin = (L == 0) ? emb : h_buf;
        gemm_kernel<<<gemm_blocks, 256>>>(hin, convW + L * HID * HID, m_buf, n);
        aggregate_kernel<<<agg_blocks, 256>>>(m_buf, convB + L * HID,
                                              lnG + L * HID, lnB + L * HID, h_buf, n);
    }

    pool_kernel<<<(n * HID + 255) / 256, 256>>>(h_buf, batch, n);
    mlp_kernel<<<NG, HID>>>(W1, b1, W2, b2, out);
}

// round 3
// speedup vs baseline: 1.0502x; 1.0502x over previous
#include <cuda_runtime.h>

#define NN   50000
#define NE   1250000
#define HID  64
#define NL   3
#define NG   64
#define EPSV 1e-5f

// -------- device scratch (no runtime allocation allowed) --------
__device__ float d_h0[NN * HID];
__device__ float d_h1[NN * HID];
__device__ int2  d_epk[NE];      // packed (src, weight-bits) grouped by dst
__device__ int   d_deg[NN];
__device__ int   d_ptr[NN + 1];
__device__ int   d_cur[NN];
__device__ float d_psum[NG * HID];
__device__ int   d_pmax[NG * HID];   // float bits; post-ReLU values >= 0 so int-max works
__device__ int   d_pcnt[NG];

// -------- zero the per-launch scratch --------
__global__ void zero_kernel() {
    int i = blockIdx.x * blockDim.x + threadIdx.x;
    int stride = gridDim.x * blockDim.x;
    for (int k = i; k < NN; k += stride) d_deg[k] = 0;
    for (int k = i; k < NG * HID; k += stride) { d_psum[k] = 0.f; d_pmax[k] = 0; }
    if (i < NG) d_pcnt[i] = 0;
}

// -------- CSR build: count degrees of dst --------
__global__ void count_kernel(const int* __restrict__ dst, int ne) {
    int e = blockIdx.x * blockDim.x + threadIdx.x;
    if (e < ne) atomicAdd(&d_deg[dst[e]], 1);
}

// -------- single-block exclusive scan over degrees --------
__global__ void scan_kernel(int n) {
    __shared__ int sm[1024];
    const int CH = (NN + 1023) / 1024;  // 49
    int t = threadIdx.x;
    int start = t * CH;
    int s = 0;
#pragma unroll 7
    for (int i = 0; i < CH; i++) {
        int idx = start + i;
        if (idx < n) s += d_deg[idx];
    }
    sm[t] = s;
    __syncthreads();
    for (int off = 1; off < 1024; off <<= 1) {
        int v = (t >= off) ? sm[t - off] : 0;
        __syncthreads();
        sm[t] += v;
        __syncthreads();
    }
    int run = (t == 0) ? 0 : sm[t - 1];
    for (int i = 0; i < CH; i++) {
        int idx = start + i;
        if (idx < n) {
            d_ptr[idx] = run;
            d_cur[idx] = run;
            run += d_deg[idx];
        }
    }
    if (t == 1023) d_ptr[n] = sm[1023];
}

// -------- CSR build: scatter packed (src, w) grouped by dst (one 8B store) --
__global__ void scatter_kernel(const int* __restrict__ src, const int* __restrict__ dst,
                               const float* __restrict__ w, int ne) {
    int e = blockIdx.x * blockDim.x + threadIdx.x;
    if (e < ne) {
        int d = dst[e];
        int p = atomicAdd(&d_cur[d], 1);
        d_epk[p] = make_int2(src[e], __float_as_int(w[e]));
    }
}

// -------- fused layer: aggregate(h) -> @W -> +b -> LN -> ReLU [-> pool] -----
// One warp per node; grid-stride. hin and hout are ALWAYS distinct buffers
// (ping-pong), and the pooled last layer writes no node features at all.
__global__ void fused_layer_kernel(const float* __restrict__ hin,
                                   const float* __restrict__ W,
                                   const float* __restrict__ cB,
                                   const float* __restrict__ lg,
                                   const float* __restrict__ lb,
                                   float* __restrict__ hout,
                                   const int* __restrict__ batch,
                                   int do_pool, int n) {
    __shared__ float Ws[HID * HID];
    __shared__ float sB[HID], sG[HID], sLb[HID];
    int t = threadIdx.x;
    for (int i = t; i < HID * HID; i += blockDim.x) Ws[i] = W[i];
    if (t < HID) { sB[t] = cB[t]; sG[t] = lg[t]; sLb[t] = lb[t]; }
    __syncthreads();

    int warp = t >> 5, lane = t & 31;
    int nwarp = blockDim.x >> 5;

    for (int node = blockIdx.x * nwarp + warp; node < n; node += gridDim.x * nwarp) {
        int beg = d_ptr[node], end = d_ptr[node + 1];
        float ax = 0.f, ay = 0.f;
        int e = beg;
        // unroll-by-4: batch the packed-edge loads + gathers to raise MLP
        for (; e + 4 <= end; e += 4) {
            int2 p0 = d_epk[e + 0];
            int2 p1 = d_epk[e + 1];
            int2 p2 = d_epk[e + 2];
            int2 p3 = d_epk[e + 3];
            float2 v0 = ((const float2*)(hin + (size_t)p0.x * HID))[lane];
            float2 v1 = ((const float2*)(hin + (size_t)p1.x * HID))[lane];
            float2 v2 = ((const float2*)(hin + (size_t)p2.x * HID))[lane];
            float2 v3 = ((const float2*)(hin + (size_t)p3.x * HID))[lane];
            float w0 = __int_as_float(p0.y), w1 = __int_as_float(p1.y);
            float w2 = __int_as_float(p2.y), w3 = __int_as_float(p3.y);
            ax += v0.x * w0; ay += v0.y * w0;
            ax += v1.x * w1; ay += v1.y * w1;
            ax += v2.x * w2; ay += v2.y * w2;
            ax += v3.x * w3; ay += v3.y * w3;
        }
        for (; e < end; e++) {
            int2 p = d_epk[e];
            float2 v = ((const float2*)(hin + (size_t)p.x * HID))[lane];
            float w = __int_as_float(p.y);
            ax += v.x * w; ay += v.y * w;
        }

        // in-warp GEMM: y = a @ W, a distributed 2 elems/lane
        float accx = 0.f, accy = 0.f;
#pragma unroll
        for (int k2 = 0; k2 < 32; k2++) {
            float hx = __shfl_sync(0xffffffffu, ax, k2);
            float hy = __shfl_sync(0xffffffffu, ay, k2);
            float2 w0 = ((const float2*)(Ws + (2 * k2) * HID))[lane];
            float2 w1 = ((const float2*)(Ws + (2 * k2 + 1) * HID))[lane];
            accx += hx * w0.x; accy += hx * w0.y;
            accx += hy * w1.x; accy += hy * w1.y;
        }
        accx += sB[2 * lane];
        accy += sB[2 * lane + 1];

        // LayerNorm over 64 + ReLU
        float sum = accx + accy;
#pragma unroll
        for (int o = 16; o > 0; o >>= 1) sum += __shfl_xor_sync(0xffffffffu, sum, o);
        float mu = sum * (1.f / 64.f);
        float dx = accx - mu, dy = accy - mu;
        float v2 = dx * dx + dy * dy;
#pragma unroll
        for (int o = 16; o > 0; o >>= 1) v2 += __shfl_xor_sync(0xffffffffu, v2, o);
        float inv = rsqrtf(v2 * (1.f / 64.f) + EPSV);
        float rx = fmaxf(dx * inv * sG[2 * lane] + sLb[2 * lane], 0.f);
        float ry = fmaxf(dy * inv * sG[2 * lane + 1] + sLb[2 * lane + 1], 0.f);

        if (do_pool) {
            int b = batch[node];
            atomicAdd(&d_psum[b * HID + 2 * lane], rx);
            atomicAdd(&d_psum[b * HID + 2 * lane + 1], ry);
            atomicMax(&d_pmax[b * HID + 2 * lane], __float_as_int(rx));
            atomicMax(&d_pmax[b * HID + 2 * lane + 1], __float_as_int(ry));
            if (lane == 0) atomicAdd(&d_pcnt[b], 1);
        } else {
            ((float2*)(hout + (size_t)node * HID))[lane] = make_float2(rx, ry);
        }
    }
}

// -------- final MLP: out[g] = relu([mean||max] @ W1 + b1) @ W2 + b2 --------
__global__ void mlp_kernel(const float* __restrict__ W1, const float* __restrict__ b1,
                           const float* __restrict__ W2, const float* __restrict__ b2,
                           float* __restrict__ out) {
    __shared__ float g[2 * HID];
    __shared__ float hr[HID];
    int gi = blockIdx.x, j = threadIdx.x;
    int cnt = d_pcnt[gi];
    float c = fmaxf((float)cnt, 1.f);
    g[j] = d_psum[gi * HID + j] / c;
    g[HID + j] = (cnt > 0) ? __int_as_float(d_pmax[gi * HID + j]) : 0.f;
    __syncthreads();
    float acc = b1[j];
#pragma unroll
    for (int k = 0; k < 2 * HID; k++) acc += g[k] * W1[k * HID + j];
    acc = fmaxf(acc, 0.f);
    hr[j] = acc * W2[j];
    __syncthreads();
    if (j < 32) {
        float s = hr[j] + hr[j + 32];
#pragma unroll
        for (int o = 16; o > 0; o >>= 1) s += __shfl_xor_sync(0xffffffffu, s, o);
        if (j == 0) out[gi] = s + b2[0];
    }
}

extern "C" void kernel_launch(void* const* d_in, const int* in_sizes, int n_in,
                              void* d_out, int out_size) {
    // input order: x, edge_index, edge_weight, batch, emb, convW, convB, lnG, lnB, W1, b1, W2, b2
    const int*   edge_index = (const int*)d_in[1];
    const float* edge_w     = (const float*)d_in[2];
    const int*   batch      = (const int*)d_in[3];
    const float* emb        = (const float*)d_in[4];
    const float* convW      = (const float*)d_in[5];
    const float* convB      = (const float*)d_in[6];
    const float* lnG        = (const float*)d_in[7];
    const float* lnB        = (const float*)d_in[8];
    const float* W1         = (const float*)d_in[9];
    const float* b1         = (const float*)d_in[10];
    const float* W2         = (const float*)d_in[11];
    const float* b2         = (const float*)d_in[12];
    float* out = (float*)d_out;

    int ne = in_sizes[2];            // N_EDGES
    int n  = in_sizes[3];            // N_NODES
    const int* src = edge_index;
    const int* dst = edge_index + ne;

    float *h0, *h1;
    cudaGetSymbolAddress((void**)&h0, d_h0);
    cudaGetSymbolAddress((void**)&h1, d_h1);

    zero_kernel<<<256, 256>>>();
    count_kernel<<<(ne + 255) / 256, 256>>>(dst, ne);
    scan_kernel<<<1, 1024>>>(n);
    scatter_kernel<<<(ne + 255) / 256, 256>>>(src, dst, edge_w, ne);

    // grid-stride: ~4 nodes per warp keeps smem-W reload overhead to ~25 MB total
    const int THREADS = 256;
    const int WARPS_PER_BLK = THREADS / 32;
    int blocks = (n + 4 * WARPS_PER_BLK - 1) / (4 * WARPS_PER_BLK);   // 1563

    // ping-pong buffers: emb -> h0 -> h1 -> (pool only)
    fused_layer_kernel<<<blocks, THREADS>>>(emb, convW + 0 * HID * HID,
                                            convB + 0 * HID, lnG + 0 * HID,
                                            lnB + 0 * HID, h0, batch, 0, n);
    fused_layer_kernel<<<blocks, THREADS>>>(h0, convW + 1 * HID * HID,
                                            convB + 1 * HID, lnG + 1 * HID,
                                            lnB + 1 * HID, h1, batch, 0, n);
    fused_layer_kernel<<<blocks, THREADS>>>(h1, convW + 2 * HID * HID,
                                            convB + 2 * HID, lnG + 2 * HID,
                                            lnB + 2 * HID, (float*)nullptr, batch, 1, n);

    mlp_kernel<<<NG, HID>>>(W1, b1, W2, b2, out);
}

// round 4
// speedup vs baseline: 1.1151x; 1.0618x over previous
#include <cuda_runtime.h>
#include <cuda_fp16.h>

#define NN   50000
#define NE   1250000
#define HID  64
#define NL   3
#define NG   64
#define EPSV 1e-5f

// -------- device scratch (no runtime allocation allowed) --------
// node features stored as half2 (32 half2 = 64 halves per node, 128B/row)
__device__ unsigned int d_hhA[NN * 32];
__device__ unsigned int d_hhB[NN * 32];
__device__ int2  d_epk[NE];      // packed (src, weight-bits) grouped by dst
__device__ int   d_deg[NN];
__device__ int   d_ptr[NN + 1];
__device__ int   d_cur[NN];
__device__ float d_psum[NG * HID];
__device__ int   d_pmax[NG * HID];   // float bits; post-ReLU values >= 0 so int-max works
__device__ int   d_pcnt[NG];

// -------- zero the per-launch scratch --------
__global__ void zero_kernel() {
    int i = blockIdx.x * blockDim.x + threadIdx.x;
    int stride = gridDim.x * blockDim.x;
    for (int k = i; k < NN; k += stride) d_deg[k] = 0;
    for (int k = i; k < NG * HID; k += stride) { d_psum[k] = 0.f; d_pmax[k] = 0; }
    if (i < NG) d_pcnt[i] = 0;
}

// -------- convert emb (fp32) -> half2 table --------
__global__ void convert_kernel(const float* __restrict__ emb) {
    int i = blockIdx.x * blockDim.x + threadIdx.x;   // half2 index
    if (i < NN * 32) {
        float2 v = ((const float2*)emb)[i];
        __half2 h = __floats2half2_rn(v.x, v.y);
        d_hhA[i] = *(unsigned int*)&h;
    }
}

// -------- CSR build: count degrees of dst (4-way MLP) --------
__global__ void count_kernel(const int* __restrict__ dst, int ne, int T) {
    int t = blockIdx.x * blockDim.x + threadIdx.x;
    if (t >= T) return;
    int e0 = t, e1 = t + T, e2 = t + 2 * T, e3 = t + 3 * T;
    int d0 = (e0 < ne) ? dst[e0] : -1;
    int d1 = (e1 < ne) ? dst[e1] : -1;
    int d2 = (e2 < ne) ? dst[e2] : -1;
    int d3 = (e3 < ne) ? dst[e3] : -1;
    if (d0 >= 0) atomicAdd(&d_deg[d0], 1);
    if (d1 >= 0) atomicAdd(&d_deg[d1], 1);
    if (d2 >= 0) atomicAdd(&d_deg[d2], 1);
    if (d3 >= 0) atomicAdd(&d_deg[d3], 1);
}

// -------- single-block exclusive scan over degrees --------
__global__ void scan_kernel(int n) {
    __shared__ int sm[1024];
    const int CH = (NN + 1023) / 1024;  // 49
    int t = threadIdx.x;
    int start = t * CH;
    int s = 0;
    for (int i = 0; i < CH; i++) {
        int idx = start + i;
        if (idx < n) s += d_deg[idx];
    }
    sm[t] = s;
    __syncthreads();
    for (int off = 1; off < 1024; off <<= 1) {
        int v = (t >= off) ? sm[t - off] : 0;
        __syncthreads();
        sm[t] += v;
        __syncthreads();
    }
    int run = (t == 0) ? 0 : sm[t - 1];
    for (int i = 0; i < CH; i++) {
        int idx = start + i;
        if (idx < n) {
            d_ptr[idx] = run;
            d_cur[idx] = run;
            run += d_deg[idx];
        }
    }
    if (t == 1023) d_ptr[n] = sm[1023];
}

// -------- CSR build: scatter packed (src, w) grouped by dst (4-way MLP) ----
__global__ void scatter_kernel(const int* __restrict__ src, const int* __restrict__ dst,
                               const float* __restrict__ w, int ne, int T) {
    int t = blockIdx.x * blockDim.x + threadIdx.x;
    if (t >= T) return;
    int e0 = t, e1 = t + T, e2 = t + 2 * T, e3 = t + 3 * T;
    int d0 = (e0 < ne) ? dst[e0] : -1;
    int d1 = (e1 < ne) ? dst[e1] : -1;
    int d2 = (e2 < ne) ? dst[e2] : -1;
    int d3 = (e3 < ne) ? dst[e3] : -1;
    int s0 = (e0 < ne) ? src[e0] : 0;
    int s1 = (e1 < ne) ? src[e1] : 0;
    int s2 = (e2 < ne) ? src[e2] : 0;
    int s3 = (e3 < ne) ? src[e3] : 0;
    float w0 = (e0 < ne) ? w[e0] : 0.f;
    float w1 = (e1 < ne) ? w[e1] : 0.f;
    float w2 = (e2 < ne) ? w[e2] : 0.f;
    float w3 = (e3 < ne) ? w[e3] : 0.f;
    if (d0 >= 0) { int p = atomicAdd(&d_cur[d0], 1); d_epk[p] = make_int2(s0, __float_as_int(w0)); }
    if (d1 >= 0) { int p = atomicAdd(&d_cur[d1], 1); d_epk[p] = make_int2(s1, __float_as_int(w1)); }
    if (d2 >= 0) { int p = atomicAdd(&d_cur[d2], 1); d_epk[p] = make_int2(s2, __float_as_int(w2)); }
    if (d3 >= 0) { int p = atomicAdd(&d_cur[d3], 1); d_epk[p] = make_int2(s3, __float_as_int(w3)); }
}

__device__ __forceinline__ float2 h2f(unsigned int bits) {
    __half2 h = *(__half2*)&bits;
    return __half22float2(h);
}

// -------- fused layer: aggregate(h) -> @W -> +b -> LN -> ReLU [-> pool] -----
// One warp per node; grid-stride; fp16 feature table, fp32 math.
__global__ void __launch_bounds__(256)
fused_layer_kernel(const unsigned int* __restrict__ hin,
                   const float* __restrict__ W,
                   const float* __restrict__ cB,
                   const float* __restrict__ lg,
                   const float* __restrict__ lb,
                   unsigned int* __restrict__ hout,
                   const int* __restrict__ batch,
                   int do_pool, int n) {
    __shared__ float Ws[HID * HID];
    __shared__ float sB[HID], sG[HID], sLb[HID];
    int t = threadIdx.x;
    for (int i = t; i < HID * HID; i += blockDim.x) Ws[i] = W[i];
    if (t < HID) { sB[t] = cB[t]; sG[t] = lg[t]; sLb[t] = lb[t]; }
    __syncthreads();

    int warp = t >> 5, lane = t & 31;
    int nwarp = blockDim.x >> 5;

    for (int node = blockIdx.x * nwarp + warp; node < n; node += gridDim.x * nwarp) {
        int beg = d_ptr[node], end = d_ptr[node + 1];
        float ax = 0.f, ay = 0.f;
        int e = beg;
        // unroll-by-8: 8 outstanding 128B gathers per warp
        for (; e + 8 <= end; e += 8) {
            int2 p0 = d_epk[e + 0];
            int2 p1 = d_epk[e + 1];
            int2 p2 = d_epk[e + 2];
            int2 p3 = d_epk[e + 3];
            int2 p4 = d_epk[e + 4];
            int2 p5 = d_epk[e + 5];
            int2 p6 = d_epk[e + 6];
            int2 p7 = d_epk[e + 7];
            unsigned int g0 = __ldg(hin + (size_t)p0.x * 32 + lane);
            unsigned int g1 = __ldg(hin + (size_t)p1.x * 32 + lane);
            unsigned int g2 = __ldg(hin + (size_t)p2.x * 32 + lane);
            unsigned int g3 = __ldg(hin + (size_t)p3.x * 32 + lane);
            unsigned int g4 = __ldg(hin + (size_t)p4.x * 32 + lane);
            unsigned int g5 = __ldg(hin + (size_t)p5.x * 32 + lane);
            unsigned int g6 = __ldg(hin + (size_t)p6.x * 32 + lane);
            unsigned int g7 = __ldg(hin + (size_t)p7.x * 32 + lane);
            float2 v;
            v = h2f(g0); ax += v.x * __int_as_float(p0.y); ay += v.y * __int_as_float(p0.y);
            v = h2f(g1); ax += v.x * __int_as_float(p1.y); ay += v.y * __int_as_float(p1.y);
            v = h2f(g2); ax += v.x * __int_as_float(p2.y); ay += v.y * __int_as_float(p2.y);
            v = h2f(g3); ax += v.x * __int_as_float(p3.y); ay += v.y * __int_as_float(p3.y);
            v = h2f(g4); ax += v.x * __int_as_float(p4.y); ay += v.y * __int_as_float(p4.y);
            v = h2f(g5); ax += v.x * __int_as_float(p5.y); ay += v.y * __int_as_float(p5.y);
            v = h2f(g6); ax += v.x * __int_as_float(p6.y); ay += v.y * __int_as_float(p6.y);
            v = h2f(g7); ax += v.x * __int_as_float(p7.y); ay += v.y * __int_as_float(p7.y);
        }
        for (; e < end; e++) {
            int2 p = d_epk[e];
            unsigned int g = __ldg(hin + (size_t)p.x * 32 + lane);
            float2 v = h2f(g);
            float w = __int_as_float(p.y);
            ax += v.x * w; ay += v.y * w;
        }

        // in-warp GEMM: y = a @ W, a distributed 2 elems/lane
        float accx = 0.f, accy = 0.f;
#pragma unroll
        for (int k2 = 0; k2 < 32; k2++) {
            float hx = __shfl_sync(0xffffffffu, ax, k2);
            float hy = __shfl_sync(0xffffffffu, ay, k2);
            float2 w0 = ((const float2*)(Ws + (2 * k2) * HID))[lane];
            float2 w1 = ((const float2*)(Ws + (2 * k2 + 1) * HID))[lane];
            accx += hx * w0.x; accy += hx * w0.y;
            accx += hy * w1.x; accy += hy * w1.y;
        }
        accx += sB[2 * lane];
        accy += sB[2 * lane + 1];

        // LayerNorm over 64 + ReLU
        float sum = accx + accy;
#pragma unroll
        for (int o = 16; o > 0; o >>= 1) sum += __shfl_xor_sync(0xffffffffu, sum, o);
        float mu = sum * (1.f / 64.f);
        float dx = accx - mu, dy = accy - mu;
        float v2 = dx * dx + dy * dy;
#pragma unroll
        for (int o = 16; o > 0; o >>= 1) v2 += __shfl_xor_sync(0xffffffffu, v2, o);
        float inv = rsqrtf(v2 * (1.f / 64.f) + EPSV);
        float rx = fmaxf(dx * inv * sG[2 * lane] + sLb[2 * lane], 0.f);
        float ry = fmaxf(dy * inv * sG[2 * lane + 1] + sLb[2 * lane + 1], 0.f);

        if (do_pool) {
            int b = batch[node];
            atomicAdd(&d_psum[b * HID + 2 * lane], rx);
            atomicAdd(&d_psum[b * HID + 2 * lane + 1], ry);
            atomicMax(&d_pmax[b * HID + 2 * lane], __float_as_int(rx));
            atomicMax(&d_pmax[b * HID + 2 * lane + 1], __float_as_int(ry));
            if (lane == 0) atomicAdd(&d_pcnt[b], 1);
        } else {
            __half2 hv = __floats2half2_rn(rx, ry);
            hout[(size_t)node * 32 + lane] = *(unsigned int*)&hv;
        }
    }
}

// -------- final MLP: out[g] = relu([mean||max] @ W1 + b1) @ W2 + b2 --------
__global__ void mlp_kernel(const float* __restrict__ W1, const float* __restrict__ b1,
                           const float* __restrict__ W2, const float* __restrict__ b2,
                           float* __restrict__ out) {
    __shared__ float g[2 * HID];
    __shared__ float hr[HID];
    int gi = blockIdx.x, j = threadIdx.x;
    int cnt = d_pcnt[gi];
    float c = fmaxf((float)cnt, 1.f);
    g[j] = d_psum[gi * HID + j] / c;
    g[HID + j] = (cnt > 0) ? __int_as_float(d_pmax[gi * HID + j]) : 0.f;
    __syncthreads();
    float acc = b1[j];
#pragma unroll
    for (int k = 0; k < 2 * HID; k++) acc += g[k] * W1[k * HID + j];
    acc = fmaxf(acc, 0.f);
    hr[j] = acc * W2[j];
    __syncthreads();
    if (j < 32) {
        float s = hr[j] + hr[j + 32];
#pragma unroll
        for (int o = 16; o > 0; o >>= 1) s += __shfl_xor_sync(0xffffffffu, s, o);
        if (j == 0) out[gi] = s + b2[0];
    }
}

extern "C" void kernel_launch(void* const* d_in, const int* in_sizes, int n_in,
                              void* d_out, int out_size) {
    // input order: x, edge_index, edge_weight, batch, emb, convW, convB, lnG, lnB, W1, b1, W2, b2
    const int*   edge_index = (const int*)d_in[1];
    const float* edge_w     = (const float*)d_in[2];
    const int*   batch      = (const int*)d_in[3];
    const float* emb        = (const float*)d_in[4];
    const float* convW      = (const float*)d_in[5];
    const float* convB      = (const float*)d_in[6];
    const float* lnG        = (const float*)d_in[7];
    const float* lnB        = (const float*)d_in[8];
    const float* W1         = (const float*)d_in[9];
    const float* b1         = (const float*)d_in[10];
    const float* W2         = (const float*)d_in[11];
    const float* b2         = (const float*)d_in[12];
    float* out = (float*)d_out;

    int ne = in_sizes[2];            // N_EDGES
    int n  = in_sizes[3];            // N_NODES
    const int* src = edge_index;
    const int* dst = edge_index + ne;

    unsigned int *hA, *hB;
    cudaGetSymbolAddress((void**)&hA, d_hhA);
    cudaGetSymbolAddress((void**)&hB, d_hhB);

    zero_kernel<<<256, 256>>>();
    convert_kernel<<<(NN * 32 + 255) / 256, 256>>>(emb);
    int T = (ne + 3) / 4;
    count_kernel<<<(T + 255) / 256, 256>>>(dst, ne, T);
    scan_kernel<<<1, 1024>>>(n);
    scatter_kernel<<<(T + 255) / 256, 256>>>(src, dst, edge_w, ne, T);

    const int THREADS = 256;
    const int WARPS_PER_BLK = THREADS / 32;
    int blocks = (n + 4 * WARPS_PER_BLK - 1) / (4 * WARPS_PER_BLK);   // ~1563

    // ping-pong half2 buffers: emb->(convert)->hA ; L0: hA->hB ; L1: hB->hA ; L2: hA->pool
    fused_layer_kernel<<<blocks, THREADS>>>(hA, convW + 0 * HID * HID,
                                            convB + 0 * HID, lnG + 0 * HID,
                                            lnB + 0 * HID, hB, batch, 0, n);
    fused_layer_kernel<<<blocks, THREADS>>>(hB, convW + 1 * HID * HID,
                                            convB + 1 * HID, lnG + 1 * HID,
                                            lnB + 1 * HID, hA, batch, 0, n);
    fused_layer_kernel<<<blocks, THREADS>>>(hA, convW + 2 * HID * HID,
                                            convB + 2 * HID, lnG + 2 * HID,
                                            lnB + 2 * HID, (unsigned int*)nullptr, batch, 1, n);

    mlp_kernel<<<NG, HID>>>(W1, b1, W2, b2, out);
}

// round 5
// speedup vs baseline: 1.4247x; 1.2776x over previous
#include <cuda_runtime.h>
#include <cuda_fp16.h>

#define NN   50000
#define NE   1250000
#define HID  64
#define NL   3
#define NG   64
#define EPSV 1e-5f

#define SCAN_BS   256
#define SCAN_NBLK ((NN + SCAN_BS - 1) / SCAN_BS)   // 196

// -------- device scratch (no runtime allocation allowed) --------
__device__ unsigned int d_hhA[NN * 32];   // half2 node features (128B/row)
__device__ unsigned int d_hhB[NN * 32];
__device__ int2  d_epk[NE];      // packed (src, weight-bits) grouped by dst
__device__ int   d_deg[NN];
__device__ int   d_ptr[NN + 1];
__device__ int   d_cur[NN];
__device__ int   d_bsum[SCAN_NBLK];
__device__ int   d_boff[SCAN_NBLK];
__device__ float d_psum[NG * HID];
__device__ int   d_pmax[NG * HID];   // float bits; post-ReLU values >= 0
__device__ int   d_pcnt[NG];

// -------- zero the per-launch scratch --------
__global__ void zero_kernel() {
    int i = blockIdx.x * blockDim.x + threadIdx.x;
    int stride = gridDim.x * blockDim.x;
    for (int k = i; k < NN; k += stride) d_deg[k] = 0;
    for (int k = i; k < NG * HID; k += stride) { d_psum[k] = 0.f; d_pmax[k] = 0; }
    if (i < NG) d_pcnt[i] = 0;
}

// -------- convert emb (fp32) -> half2 table --------
__global__ void convert_kernel(const float* __restrict__ emb) {
    int i = blockIdx.x * blockDim.x + threadIdx.x;
    if (i < NN * 32) {
        float2 v = ((const float2*)emb)[i];
        __half2 h = __floats2half2_rn(v.x, v.y);
        d_hhA[i] = *(unsigned int*)&h;
    }
}

// -------- CSR build: count degrees of dst (4-way MLP) --------
__global__ void count_kernel(const int* __restrict__ dst, int ne, int T) {
    int t = blockIdx.x * blockDim.x + threadIdx.x;
    if (t >= T) return;
    int e0 = t, e1 = t + T, e2 = t + 2 * T, e3 = t + 3 * T;
    int d0 = (e0 < ne) ? dst[e0] : -1;
    int d1 = (e1 < ne) ? dst[e1] : -1;
    int d2 = (e2 < ne) ? dst[e2] : -1;
    int d3 = (e3 < ne) ? dst[e3] : -1;
    if (d0 >= 0) atomicAdd(&d_deg[d0], 1);
    if (d1 >= 0) atomicAdd(&d_deg[d1], 1);
    if (d2 >= 0) atomicAdd(&d_deg[d2], 1);
    if (d3 >= 0) atomicAdd(&d_deg[d3], 1);
}

// -------- 3-phase parallel scan --------
// Phase 1: per-block sum of degrees
__global__ void scan_phase1(int n) {
    __shared__ int sm[SCAN_BS];
    int t = threadIdx.x;
    int idx = blockIdx.x * SCAN_BS + t;
    sm[t] = (idx < n) ? d_deg[idx] : 0;
    __syncthreads();
#pragma unroll
    for (int off = SCAN_BS / 2; off > 0; off >>= 1) {
        if (t < off) sm[t] += sm[t + off];
        __syncthreads();
    }
    if (t == 0) d_bsum[blockIdx.x] = sm[0];
}

// Phase 2: single small block scans the 196 block sums (exclusive)
__global__ void scan_phase2() {
    __shared__ int sm[SCAN_NBLK];
    int t = threadIdx.x;
    if (t < SCAN_NBLK) sm[t] = d_bsum[t];
    __syncthreads();
    // Hillis-Steele inclusive over SCAN_NBLK entries (single 256-thread block)
    for (int off = 1; off < SCAN_NBLK; off <<= 1) {
        int v = (t < SCAN_NBLK && t >= off) ? sm[t - off] : 0;
        __syncthreads();
        if (t < SCAN_NBLK) sm[t] += v;
        __syncthreads();
    }
    if (t < SCAN_NBLK) d_boff[t] = (t == 0) ? 0 : sm[t - 1];
    if (t == 0) d_ptr[NN] = sm[SCAN_NBLK - 1];
}

// Phase 3: block-exclusive scan + offset -> d_ptr / d_cur
__global__ void scan_phase3(int n) {
    __shared__ int sm[SCAN_BS];
    int t = threadIdx.x;
    int idx = blockIdx.x * SCAN_BS + t;
    int v = (idx < n) ? d_deg[idx] : 0;
    sm[t] = v;
    __syncthreads();
    // Hillis-Steele inclusive
#pragma unroll
    for (int off = 1; off < SCAN_BS; off <<= 1) {
        int u = (t >= off) ? sm[t - off] : 0;
        __syncthreads();
        sm[t] += u;
        __syncthreads();
    }
    if (idx < n) {
        int p = d_boff[blockIdx.x] + sm[t] - v;   // exclusive
        d_ptr[idx] = p;
        d_cur[idx] = p;
    }
}

// -------- CSR build: scatter packed (src, w) grouped by dst (4-way MLP) ----
__global__ void scatter_kernel(const int* __restrict__ src, const int* __restrict__ dst,
                               const float* __restrict__ w, int ne, int T) {
    int t = blockIdx.x * blockDim.x + threadIdx.x;
    if (t >= T) return;
    int e0 = t, e1 = t + T, e2 = t + 2 * T, e3 = t + 3 * T;
    int d0 = (e0 < ne) ? dst[e0] : -1;
    int d1 = (e1 < ne) ? dst[e1] : -1;
    int d2 = (e2 < ne) ? dst[e2] : -1;
    int d3 = (e3 < ne) ? dst[e3] : -1;
    int s0 = (e0 < ne) ? src[e0] : 0;
    int s1 = (e1 < ne) ? src[e1] : 0;
    int s2 = (e2 < ne) ? src[e2] : 0;
    int s3 = (e3 < ne) ? src[e3] : 0;
    float w0 = (e0 < ne) ? w[e0] : 0.f;
    float w1 = (e1 < ne) ? w[e1] : 0.f;
    float w2 = (e2 < ne) ? w[e2] : 0.f;
    float w3 = (e3 < ne) ? w[e3] : 0.f;
    if (d0 >= 0) { int p = atomicAdd(&d_cur[d0], 1); d_epk[p] = make_int2(s0, __float_as_int(w0)); }
    if (d1 >= 0) { int p = atomicAdd(&d_cur[d1], 1); d_epk[p] = make_int2(s1, __float_as_int(w1)); }
    if (d2 >= 0) { int p = atomicAdd(&d_cur[d2], 1); d_epk[p] = make_int2(s2, __float_as_int(w2)); }
    if (d3 >= 0) { int p = atomicAdd(&d_cur[d3], 1); d_epk[p] = make_int2(s3, __float_as_int(w3)); }
}

__device__ __forceinline__ float2 h2f(unsigned int bits) {
    __half2 h = *(__half2*)&bits;
    return __half22float2(h);
}

// -------- fused layer: aggregate(h) -> @W -> +b -> LN -> ReLU [-> pool] -----
__global__ void __launch_bounds__(256)
fused_layer_kernel(const unsigned int* __restrict__ hin,
                   const float* __restrict__ W,
                   const float* __restrict__ cB,
                   const float* __restrict__ lg,
                   const float* __restrict__ lb,
                   unsigned int* __restrict__ hout,
                   const int* __restrict__ batch,
                   int do_pool, int n) {
    __shared__ float Ws[HID * HID];
    __shared__ float sB[HID], sG[HID], sLb[HID];
    int t = threadIdx.x;
    for (int i = t; i < HID * HID; i += blockDim.x) Ws[i] = W[i];
    if (t < HID) { sB[t] = cB[t]; sG[t] = lg[t]; sLb[t] = lb[t]; }
    __syncthreads();

    int warp = t >> 5, lane = t & 31;
    int nwarp = blockDim.x >> 5;

    for (int node = blockIdx.x * nwarp + warp; node < n; node += gridDim.x * nwarp) {
        int beg = d_ptr[node], end = d_ptr[node + 1];
        float ax = 0.f, ay = 0.f;
        int e = beg;
        for (; e + 8 <= end; e += 8) {
            int2 p0 = d_epk[e + 0];
            int2 p1 = d_epk[e + 1];
            int2 p2 = d_epk[e + 2];
            int2 p3 = d_epk[e + 3];
            int2 p4 = d_epk[e + 4];
            int2 p5 = d_epk[e + 5];
            int2 p6 = d_epk[e + 6];
            int2 p7 = d_epk[e + 7];
            unsigned int g0 = __ldg(hin + (size_t)p0.x * 32 + lane);
            unsigned int g1 = __ldg(hin + (size_t)p1.x * 32 + lane);
            unsigned int g2 = __ldg(hin + (size_t)p2.x * 32 + lane);
            unsigned int g3 = __ldg(hin + (size_t)p3.x * 32 + lane);
            unsigned int g4 = __ldg(hin + (size_t)p4.x * 32 + lane);
            unsigned int g5 = __ldg(hin + (size_t)p5.x * 32 + lane);
            unsigned int g6 = __ldg(hin + (size_t)p6.x * 32 + lane);
            unsigned int g7 = __ldg(hin + (size_t)p7.x * 32 + lane);
            float2 v;
            v = h2f(g0); ax += v.x * __int_as_float(p0.y); ay += v.y * __int_as_float(p0.y);
            v = h2f(g1); ax += v.x * __int_as_float(p1.y); ay += v.y * __int_as_float(p1.y);
            v = h2f(g2); ax += v.x * __int_as_float(p2.y); ay += v.y * __int_as_float(p2.y);
            v = h2f(g3); ax += v.x * __int_as_float(p3.y); ay += v.y * __int_as_float(p3.y);
            v = h2f(g4); ax += v.x * __int_as_float(p4.y); ay += v.y * __int_as_float(p4.y);
            v = h2f(g5); ax += v.x * __int_as_float(p5.y); ay += v.y * __int_as_float(p5.y);
            v = h2f(g6); ax += v.x * __int_as_float(p6.y); ay += v.y * __int_as_float(p6.y);
            v = h2f(g7); ax += v.x * __int_as_float(p7.y); ay += v.y * __int_as_float(p7.y);
        }
        for (; e < end; e++) {
            int2 p = d_epk[e];
            unsigned int g = __ldg(hin + (size_t)p.x * 32 + lane);
            float2 v = h2f(g);
            float w = __int_as_float(p.y);
            ax += v.x * w; ay += v.y * w;
        }

        float accx = 0.f, accy = 0.f;
#pragma unroll
        for (int k2 = 0; k2 < 32; k2++) {
            float hx = __shfl_sync(0xffffffffu, ax, k2);
            float hy = __shfl_sync(0xffffffffu, ay, k2);
            float2 w0 = ((const float2*)(Ws + (2 * k2) * HID))[lane];
            float2 w1 = ((const float2*)(Ws + (2 * k2 + 1) * HID))[lane];
            accx += hx * w0.x; accy += hx * w0.y;
            accx += hy * w1.x; accy += hy * w1.y;
        }
        accx += sB[2 * lane];
        accy += sB[2 * lane + 1];

        float sum = accx + accy;
#pragma unroll
        for (int o = 16; o > 0; o >>= 1) sum += __shfl_xor_sync(0xffffffffu, sum, o);
        float mu = sum * (1.f / 64.f);
        float dx = accx - mu, dy = accy - mu;
        float v2 = dx * dx + dy * dy;
#pragma unroll
        for (int o = 16; o > 0; o >>= 1) v2 += __shfl_xor_sync(0xffffffffu, v2, o);
        float inv = rsqrtf(v2 * (1.f / 64.f) + EPSV);
        float rx = fmaxf(dx * inv * sG[2 * lane] + sLb[2 * lane], 0.f);
        float ry = fmaxf(dy * inv * sG[2 * lane + 1] + sLb[2 * lane + 1], 0.f);

        if (do_pool) {
            int b = batch[node];
            atomicAdd(&d_psum[b * HID + 2 * lane], rx);
            atomicAdd(&d_psum[b * HID + 2 * lane + 1], ry);
            atomicMax(&d_pmax[b * HID + 2 * lane], __float_as_int(rx));
            atomicMax(&d_pmax[b * HID + 2 * lane + 1], __float_as_int(ry));
            if (lane == 0) atomicAdd(&d_pcnt[b], 1);
        } else {
            __half2 hv = __floats2half2_rn(rx, ry);
            hout[(size_t)node * 32 + lane] = *(unsigned int*)&hv;
        }
    }
}

// -------- final MLP --------
__global__ void mlp_kernel(const float* __restrict__ W1, const float* __restrict__ b1,
                           const float* __restrict__ W2, const float* __restrict__ b2,
                           float* __restrict__ out) {
    __shared__ float g[2 * HID];
    __shared__ float hr[HID];
    int gi = blockIdx.x, j = threadIdx.x;
    int cnt = d_pcnt[gi];
    float c = fmaxf((float)cnt, 1.f);
    g[j] = d_psum[gi * HID + j] / c;
    g[HID + j] = (cnt > 0) ? __int_as_float(d_pmax[gi * HID + j]) : 0.f;
    __syncthreads();
    float acc = b1[j];
#pragma unroll
    for (int k = 0; k < 2 * HID; k++) acc += g[k] * W1[k * HID + j];
    acc = fmaxf(acc, 0.f);
    hr[j] = acc * W2[j];
    __syncthreads();
    if (j < 32) {
        float s = hr[j] + hr[j + 32];
#pragma unroll
        for (int o = 16; o > 0; o >>= 1) s += __shfl_xor_sync(0xffffffffu, s, o);
        if (j == 0) out[gi] = s + b2[0];
    }
}

extern "C" void kernel_launch(void* const* d_in, const int* in_sizes, int n_in,
                              void* d_out, int out_size) {
    const int*   edge_index = (const int*)d_in[1];
    const float* edge_w     = (const float*)d_in[2];
    const int*   batch      = (const int*)d_in[3];
    const float* emb        = (const float*)d_in[4];
    const float* convW      = (const float*)d_in[5];
    const float* convB      = (const float*)d_in[6];
    const float* lnG        = (const float*)d_in[7];
    const float* lnB        = (const float*)d_in[8];
    const float* W1         = (const float*)d_in[9];
    const float* b1         = (const float*)d_in[10];
    const float* W2         = (const float*)d_in[11];
    const float* b2         = (const float*)d_in[12];
    float* out = (float*)d_out;

    int ne = in_sizes[2];
    int n  = in_sizes[3];
    const int* src = edge_index;
    const int* dst = edge_index + ne;

    unsigned int *hA, *hB;
    cudaGetSymbolAddress((void**)&hA, d_hhA);
    cudaGetSymbolAddress((void**)&hB, d_hhB);

    zero_kernel<<<256, 256>>>();
    convert_kernel<<<(NN * 32 + 255) / 256, 256>>>(emb);
    int T = (ne + 3) / 4;
    count_kernel<<<(T + 255) / 256, 256>>>(dst, ne, T);
    scan_phase1<<<SCAN_NBLK, SCAN_BS>>>(n);
    scan_phase2<<<1, SCAN_BS>>>();
    scan_phase3<<<SCAN_NBLK, SCAN_BS>>>(n);
    scatter_kernel<<<(T + 255) / 256, 256>>>(src, dst, edge_w, ne, T);

    const int THREADS = 256;
    const int WARPS_PER_BLK = THREADS / 32;
    int blocks = (n + 4 * WARPS_PER_BLK - 1) / (4 * WARPS_PER_BLK);

    fused_layer_kernel<<<blocks, THREADS>>>(hA, convW + 0 * HID * HID,
                                            convB + 0 * HID, lnG + 0 * HID,
                                            lnB + 0 * HID, hB, batch, 0, n);
    fused_layer_kernel<<<blocks, THREADS>>>(hB, convW + 1 * HID * HID,
                                            convB + 1 * HID, lnG + 1 * HID,
                                            lnB + 1 * HID, hA, batch, 0, n);
    fused_layer_kernel<<<blocks, THREADS>>>(hA, convW + 2 * HID * HID,
                                            convB + 2 * HID, lnG + 2 * HID,
                                            lnB + 2 * HID, (unsigned int*)nullptr, batch, 1, n);

    mlp_kernel<<<NG, HID>>>(W1, b1, W2, b2, out);
}